// round 7
// baseline (speedup 1.0000x reference)
#include <cuda_runtime.h>
#include <math.h>
#include <stdint.h>

#define BB 4
#define LL 2048
#define CC 1024
#define C3 3072

// Scratch (device globals are the sanctioned scratch mechanism)
__device__ float g_qkv[(size_t)BB * LL * C3];   // 96 MB (tf32-rounded)
__device__ float g_attn[(size_t)BB * LL * LL];  // 64 MB (softmax out tf32-rounded)
__device__ float g_o[(size_t)BB * LL * CC];     // 32 MB (tf32-rounded)
__device__ float g_vt[(size_t)BB * CC * LL];    // 32 MB V transposed, K-major
__device__ float g_x[(size_t)BB * LL * CC];     // 32 MB x tf32-rounded
__device__ float g_wq[(size_t)C3 * CC];         // 12 MB w_qkv tf32-rounded
__device__ float g_wo[(size_t)CC * CC];         //  4 MB w_out tf32-rounded

// ---------------- helpers ----------------
__device__ __forceinline__ uint32_t smem_u32(const void* p) {
    uint32_t a;
    asm("{ .reg .u64 t; cvta.to.shared.u64 t, %1; cvt.u32.u64 %0, t; }" : "=r"(a) : "l"(p));
    return a;
}
__device__ __forceinline__ uint32_t f2tf(float f) {  // fp32 -> tf32, round-to-nearest
    uint32_t r;
    asm("cvt.rna.tf32.f32 %0, %1;" : "=r"(r) : "f"(f));
    return r;
}
__device__ __forceinline__ uint32_t swz(uint32_t off) {  // 128B-row XOR swizzle
    return off ^ ((off >> 3) & 0x70);
}
__device__ __forceinline__ void ldsm4(uint32_t (&r)[4], uint32_t addr) {
    asm volatile("ldmatrix.sync.aligned.m8n8.x4.shared.b16 {%0,%1,%2,%3}, [%4];"
                 : "=r"(r[0]), "=r"(r[1]), "=r"(r[2]), "=r"(r[3]) : "r"(addr));
}
__device__ __forceinline__ void mma_tf32(float (&d)[4], const uint32_t (&a)[4],
                                         const uint32_t b0, const uint32_t b1) {
    asm volatile("mma.sync.aligned.m16n8k8.row.col.f32.tf32.tf32.f32 "
                 "{%0,%1,%2,%3}, {%4,%5,%6,%7}, {%8,%9}, {%0,%1,%2,%3};"
                 : "+f"(d[0]), "+f"(d[1]), "+f"(d[2]), "+f"(d[3])
                 : "r"(a[0]), "r"(a[1]), "r"(a[2]), "r"(a[3]), "r"(b0), "r"(b1));
}
#define CPA16(dst, src) \
    asm volatile("cp.async.cg.shared.global [%0], [%1], 16;" :: "r"(dst), "l"(src) : "memory")
#define CPA_COMMIT() asm volatile("cp.async.commit_group;" ::: "memory")
template <int N>
__device__ __forceinline__ void cpa_wait() {
    asm volatile("cp.async.wait_group %0;" :: "n"(N) : "memory");
}

// CTA tile 128(M) x 256(N), k32 chunks. A tile 16KB, B tile 32KB, XOR-swizzled 128B rows.
// 4 stages x 48KB = 192KB dynamic smem, 1 CTA/SM.
#define TILE_A      16384
#define TILE_B      32768
#define STAGE_BYTES (TILE_A + TILE_B)
#define NSTAGE      4
#define SMEM_DYN    (NSTAGE * STAGE_BYTES)

// ---------------- tf32 mma.sync GEMM (both operands K-major, cp.async 4-stage) ----------------
// C[m0..+128, n0..+256] = scale * A(rows m0.., lda) . B(rows n0.., ldb)^T
// Inputs MUST be tf32-pre-rounded fp32. Ksz multiple of 32, >= 128.
// MASK: causal -inf where col > row. ROUND: tf32-round outputs (for downstream GEMMs).
template <bool MASK, bool ROUND>
__device__ __forceinline__ void tc_gemm(const float* __restrict__ A, int lda,
                                        const float* __restrict__ B, int ldb,
                                        float* __restrict__ C, int ldc,
                                        int Ksz, int m0, int n0, float scale)
{
    extern __shared__ __align__(128) float dsm[];
    const uint32_t sb = smem_u32(dsm);

    const int tid = threadIdx.x;
    const int ln = tid & 31, wid = tid >> 5;
    const int wm = wid >> 2, wn = wid & 3;     // warp tile origin (wm*64, wn*64)
    const int gid = ln >> 2, tig = ln & 3;

    // cp.async coords: 2 threads per 128B row; thread does 4 consecutive 16B cols
    const int rCp = tid >> 1, cg0 = (tid & 1) * 4;

    // ldmatrix invariant pieces
    const int rowAf = wm * 64 + (ln & 7) + ((ln >> 3) & 1) * 8;
    const int colA16 = ln >> 4;
    const int rowBf = wn * 64 + (ln & 7) + ((ln >> 4) & 1) * 8;
    const int colB16 = (ln >> 3) & 1;

    float acc[4][8][4];
#pragma unroll
    for (int i = 0; i < 4; i++)
#pragma unroll
        for (int j = 0; j < 8; j++)
#pragma unroll
            for (int e = 0; e < 4; e++) acc[i][j][e] = 0.f;

    const int nch = Ksz >> 5;   // k32 chunks (all call sites have nch >= 4)

    auto issue_chunk = [&](int kc, int s) {
        const uint32_t st = sb + (uint32_t)(s * STAGE_BYTES);
        const float* gA = A + (size_t)(m0 + rCp) * lda + kc * 32;
        const float* gB = B + (size_t)(n0 + rCp) * ldb + kc * 32;
        const float* gB2 = gB + (size_t)128 * ldb;
#pragma unroll
        for (int h = 0; h < 4; h++) {
            const int c16 = cg0 + h;
            CPA16(st + swz((uint32_t)(rCp * 128 + c16 * 16)), gA + c16 * 4);
            CPA16(st + TILE_A + swz((uint32_t)(rCp * 128 + c16 * 16)), gB + c16 * 4);
            CPA16(st + TILE_A + swz((uint32_t)((rCp + 128) * 128 + c16 * 16)), gB2 + c16 * 4);
        }
        CPA_COMMIT();
    };

    auto compute_k8 = [&](int s, int q) {
        const uint32_t aB = sb + (uint32_t)(s * STAGE_BYTES);
        const uint32_t bB = aB + TILE_A;
        uint32_t af[4][4];
#pragma unroll
        for (int i = 0; i < 4; i++)
            ldsm4(af[i], aB + swz((uint32_t)((rowAf + i * 16) * 128 + q * 32 + colA16 * 16)));
        uint32_t bf[8][2];
#pragma unroll
        for (int p = 0; p < 4; ++p) {
            uint32_t qq[4];
            ldsm4(qq, bB + swz((uint32_t)((rowBf + p * 16) * 128 + q * 32 + colB16 * 16)));
            bf[2 * p][0] = qq[0]; bf[2 * p][1] = qq[1];
            bf[2 * p + 1][0] = qq[2]; bf[2 * p + 1][1] = qq[3];
        }
#pragma unroll
        for (int i = 0; i < 4; i++)
#pragma unroll
            for (int j = 0; j < 8; j++)
                mma_tf32(acc[i][j], af[i], bf[j][0], bf[j][1]);
    };

    // prologue: 3 chunks in flight
    issue_chunk(0, 0);
    issue_chunk(1, 1);
    issue_chunk(2, 2);

    int s = 0;
    for (int c = 0; c < nch; ++c) {
        cpa_wait<2>();          // chunk c's group complete (2 groups may pend)
        __syncthreads();        // cross-thread visibility; also closes WAR on stage (s+3)&3
        if (c + 3 < nch) issue_chunk(c + 3, (s + 3) & 3);
        else CPA_COMMIT();      // keep group accounting uniform
#pragma unroll
        for (int q = 0; q < 4; ++q) compute_k8(s, q);
        s = (s + 1) & 3;
    }

    // ---- epilogue: registers -> gmem (float2 stores) ----
#pragma unroll
    for (int i = 0; i < 4; i++) {
        const int row0 = m0 + wm * 64 + i * 16 + gid;
#pragma unroll
        for (int j = 0; j < 8; j++) {
            const int col = n0 + wn * 64 + j * 8 + 2 * tig;
            float2 v0, v1;
            v0.x = acc[i][j][0] * scale; v0.y = acc[i][j][1] * scale;
            v1.x = acc[i][j][2] * scale; v1.y = acc[i][j][3] * scale;
            if (MASK) {
                if (col > row0)         v0.x = -INFINITY;
                if (col + 1 > row0)     v0.y = -INFINITY;
                if (col > row0 + 8)     v1.x = -INFINITY;
                if (col + 1 > row0 + 8) v1.y = -INFINITY;
            }
            if (ROUND) {
                v0.x = __uint_as_float(f2tf(v0.x)); v0.y = __uint_as_float(f2tf(v0.y));
                v1.x = __uint_as_float(f2tf(v1.x)); v1.y = __uint_as_float(f2tf(v1.y));
            }
            *(float2*)(C + (size_t)row0 * ldc + col) = v0;
            *(float2*)(C + (size_t)(row0 + 8) * ldc + col) = v1;
        }
    }
}

// ---------------- small prep kernels ----------------
__global__ void __launch_bounds__(256) k_round(const float* __restrict__ in,
                                               float* __restrict__ out, int n4) {
    int i = blockIdx.x * 256 + threadIdx.x;
    int stride = gridDim.x * 256;
    for (; i < n4; i += stride) {
        float4 v = ((const float4*)in)[i];
        v.x = __uint_as_float(f2tf(v.x)); v.y = __uint_as_float(f2tf(v.y));
        v.z = __uint_as_float(f2tf(v.z)); v.w = __uint_as_float(f2tf(v.w));
        ((float4*)out)[i] = v;
    }
}

// V slice of g_qkv [b][l][2048+c] -> g_vt [b][c][l]
__global__ void __launch_bounds__(256) k_transpose_v() {
    __shared__ float tile[32][33];
    const int b = blockIdx.z;
    const int c0 = blockIdx.x * 32, l0 = blockIdx.y * 32;
    const int tx = threadIdx.x, ty = threadIdx.y;
#pragma unroll
    for (int i = 0; i < 4; i++) {
        int l = l0 + ty + i * 8;
        tile[ty + i * 8][tx] = g_qkv[((size_t)b * LL + l) * C3 + 2 * CC + c0 + tx];
    }
    __syncthreads();
#pragma unroll
    for (int i = 0; i < 4; i++) {
        int c = c0 + ty + i * 8;
        g_vt[((size_t)b * CC + c) * LL + l0 + tx] = tile[tx][ty + i * 8];
    }
}

// ---------------- stage kernels ----------------
__global__ void __launch_bounds__(256, 1) k_qkv() {
    tc_gemm<false, true>(g_x, CC, g_wq, CC, g_qkv, C3, CC,
                         blockIdx.y * 128, blockIdx.x * 256, 1.f);
}

__global__ void __launch_bounds__(256, 1) k_score() {
    const int b = blockIdx.z;
    const int m0 = blockIdx.y * 128, n0 = blockIdx.x * 256;
    if (n0 > m0 + 127) return;  // fully-masked 128x256 block
    const float* Q = g_qkv + (size_t)b * LL * C3;
    tc_gemm<true, false>(Q, C3, Q + CC, C3, g_attn + (size_t)b * LL * LL, LL, CC,
                         m0, n0, 0.03125f);
}

__global__ void __launch_bounds__(256) softmax_kernel() {
    int q = blockIdx.x, b = blockIdx.y;
    float* row = g_attn + ((size_t)b * LL + q) * LL;
    int kend = ((q >> 7) + 1) << 7;
    int tid = threadIdx.x;

    float v[8];
#pragma unroll
    for (int i = 0; i < 8; i++) {
        int k = tid + i * 256;
        v[i] = (k < kend) ? row[k] : -INFINITY;
    }
    float m = -INFINITY;
#pragma unroll
    for (int i = 0; i < 8; i++) m = fmaxf(m, v[i]);

    __shared__ float sred[8];
#pragma unroll
    for (int o = 16; o; o >>= 1) m = fmaxf(m, __shfl_xor_sync(0xffffffffu, m, o));
    if ((tid & 31) == 0) sred[tid >> 5] = m;
    __syncthreads();
    if (tid < 32) {
        float x = (tid < 8) ? sred[tid] : -INFINITY;
#pragma unroll
        for (int o = 4; o; o >>= 1) x = fmaxf(x, __shfl_xor_sync(0xffffffffu, x, o));
        if (tid == 0) sred[0] = x;
    }
    __syncthreads();
    m = sred[0];
    __syncthreads();

    float s = 0.f;
#pragma unroll
    for (int i = 0; i < 8; i++) { v[i] = expf(v[i] - m); s += v[i]; }
#pragma unroll
    for (int o = 16; o; o >>= 1) s += __shfl_xor_sync(0xffffffffu, s, o);
    if ((tid & 31) == 0) sred[tid >> 5] = s;
    __syncthreads();
    if (tid < 32) {
        float x = (tid < 8) ? sred[tid] : 0.f;
#pragma unroll
        for (int o = 4; o; o >>= 1) x += __shfl_xor_sync(0xffffffffu, x, o);
        if (tid == 0) sred[0] = x;
    }
    __syncthreads();
    float inv = 1.0f / sred[0];
#pragma unroll
    for (int i = 0; i < 8; i++) {
        int k = tid + i * 256;
        if (k < kend) row[k] = __uint_as_float(f2tf(v[i] * inv));  // pre-round for pv
    }
}

__global__ void __launch_bounds__(256, 1) k_pv() {
    const int b = blockIdx.z;
    // longest-K tiles first (K = m0 + 128 grows with m0)
    const int by = gridDim.y - 1 - blockIdx.y;
    const int m0 = by * 128, n0 = blockIdx.x * 256;
    const float* P = g_attn + (size_t)b * LL * LL;
    const float* Vt = g_vt + (size_t)b * CC * LL;
    tc_gemm<false, true>(P, LL, Vt, LL, g_o + (size_t)b * LL * CC, CC,
                         m0 + 128 /* causal K truncation */, m0, n0, 1.f);
}

__global__ void __launch_bounds__(256, 1) k_out(float* __restrict__ y) {
    tc_gemm<false, false>(g_o, CC, g_wo, CC, y, CC, CC,
                          blockIdx.y * 128, blockIdx.x * 256, 1.f);
}

extern "C" void kernel_launch(void* const* d_in, const int* in_sizes, int n_in,
                              void* d_out, int out_size)
{
    const float* x     = (const float*)d_in[0];
    const float* w_qkv = (const float*)d_in[1];
    const float* w_out = (const float*)d_in[2];
    float* y = (float*)d_out;

    static int configured = 0;
    if (!configured) {
        cudaFuncSetAttribute(k_qkv,   cudaFuncAttributeMaxDynamicSharedMemorySize, SMEM_DYN);
        cudaFuncSetAttribute(k_score, cudaFuncAttributeMaxDynamicSharedMemorySize, SMEM_DYN);
        cudaFuncSetAttribute(k_pv,    cudaFuncAttributeMaxDynamicSharedMemorySize, SMEM_DYN);
        cudaFuncSetAttribute(k_out,   cudaFuncAttributeMaxDynamicSharedMemorySize, SMEM_DYN);
        configured = 1;
    }

    float* gx;  cudaGetSymbolAddress((void**)&gx,  g_x);
    float* gwq; cudaGetSymbolAddress((void**)&gwq, g_wq);
    float* gwo; cudaGetSymbolAddress((void**)&gwo, g_wo);

    k_round<<<512, 256>>>(x,     gx,  (BB * LL * CC) / 4);
    k_round<<<512, 256>>>(w_qkv, gwq, (C3 * CC) / 4);
    k_round<<<256, 256>>>(w_out, gwo, (CC * CC) / 4);

    k_qkv<<<dim3(C3 / 256, (BB * LL) / 128), 256, SMEM_DYN>>>();
    k_transpose_v<<<dim3(CC / 32, LL / 32, BB), dim3(32, 8)>>>();
    k_score<<<dim3(LL / 256, LL / 128, BB), 256, SMEM_DYN>>>();
    softmax_kernel<<<dim3(LL, BB), 256>>>();
    k_pv<<<dim3(CC / 256, LL / 128, BB), 256, SMEM_DYN>>>();
    k_out<<<dim3(CC / 256, (BB * LL) / 128), 256, SMEM_DYN>>>(y);
}